// round 14
// baseline (speedup 1.0000x reference)
#include <cuda_runtime.h>
#include <stdint.h>
#include <math_constants.h>

// QueryDepthPoint: depth-constrained radius search.  B=8, N=16384, M=2048,
// NSAMPLE=64, DIS_Z=0.5.  Output (solved R12): f32 buffer, idx (B,M,64) at
// [0,1048576), pts_cnt (B,M) at [1048576,1064960).
//
// R13: 128-chunk prefilter -> 27.1us (occ 33.6%, issue 46%).
// R14: (1) 64-element chunks: 2x finer prefilter kills the |z2|~2.5-3.2 tail
//          (candidate prob 0.55 -> 0.33 at z2~3, ~40% less tail scan work);
//      (2) 64-thread blocks: tail warps stop stranding 7 sibling warps.

#define QB 8
#define QN 16384
#define QM 2048
#define QNS 64
#define QDIS_Z 0.5f
#define CHUNK 64
#define NCHUNK (QN / CHUNK)            // 256 chunks per batch row

__device__ float2 g_bounds[QB * NCHUNK];   // [b][chunk] = (min, max) of z1

__global__ void __launch_bounds__(256)
bounds_kernel(const float* __restrict__ xyz1)
{
    const int warp = (blockIdx.x * blockDim.x + threadIdx.x) >> 5;  // 0..2047
    const int lane = threadIdx.x & 31;
    if (warp >= QB * NCHUNK) return;
    const int b = warp >> 8;           // /256
    const int chunk = warp & 255;
    const float* __restrict__ z1 = xyz1 + b * 3 * QN + 2 * QN + chunk * CHUNK;

    float v0 = z1[lane];
    float v1 = z1[32 + lane];
    float mn = fminf(v0, v1), mx = fmaxf(v0, v1);
    #pragma unroll
    for (int off = 16; off; off >>= 1) {
        mn = fminf(mn, __shfl_xor_sync(0xFFFFFFFFu, mn, off));
        mx = fmaxf(mx, __shfl_xor_sync(0xFFFFFFFFu, mx, off));
    }
    if (lane == 0)
        g_bounds[b * NCHUNK + chunk] = make_float2(mn, mx);
}

__global__ void __launch_bounds__(64)
qdp_kernel(const float* __restrict__ xyz1, int n1,
           const float* __restrict__ xyz2, int n2,
           float* __restrict__ idx_out,
           float* __restrict__ cnt_out)
{
    const int warp_id = (blockIdx.x * blockDim.x + threadIdx.x) >> 5;
    const int lane = threadIdx.x & 31;
    if (warp_id >= QB * QM) return;
    const int b = warp_id / QM;
    const int m = warp_id - b * QM;

    const int z1_base = b * 3 * QN + 2 * QN;
    const float* __restrict__ z1 =
        (z1_base + QN <= n1) ? (xyz1 + z1_base) : xyz1;
    int z2_i = b * 3 * QM + 2 * QM + m;
    if (z2_i >= n2) z2_i = (n2 > 0) ? (n2 - 1) : 0;
    const float z2v = __ldg(&xyz2[z2_i]);

    float* __restrict__ out = idx_out + warp_id * QNS;

    const unsigned full = 0xFFFFFFFFu;
    const unsigned lt_mask = (lane == 0) ? 0u : (0xFFFFFFFFu >> (32 - lane));

    // ---- Candidate-chunk mask: 8 ballots cover 256 chunks of 64 ----
    // Widened by 5e-4: float rounding of (v - z2) can never cause a false
    // skip; false candidates only waste a scan.
    const float2* __restrict__ bnd = g_bounds + b * NCHUNK;
    const float lo = z2v - (QDIS_Z + 5e-4f);
    const float hi = z2v + (QDIS_Z + 5e-4f);
    unsigned cand[8];
    #pragma unroll
    for (int g = 0; g < 8; g++) {
        float2 mb = bnd[g * 32 + lane];
        cand[g] = __ballot_sync(full, (mb.x < hi) && (mb.y > lo));
    }

    int cnt = 0;          // warp-uniform
    int firstj = 0;       // warp-uniform

    #pragma unroll 1
    for (int g = 0; g < 8; g++) {
        unsigned cm = cand[g];
        while (cm) {      // candidate chunks in ascending order
            const int k = __ffs(cm) - 1;
            cm &= cm - 1;
            const int j0 = (g * 32 + k) * CHUNK;

            // 2 independent coalesced 128B loads (one 64-elem chunk)
            float v0 = z1[j0 +  0 + lane];
            float v1 = z1[j0 + 32 + lane];
            unsigned mk0 = __ballot_sync(full, fabsf(v0 - z2v) < QDIS_Z);
            unsigned mk1 = __ballot_sync(full, fabsf(v1 - z2v) < QDIS_Z);

            if (mk0) {   // warp-uniform
                if (cnt == 0) firstj = j0 + __ffs(mk0) - 1;
                int pos = cnt + __popc(mk0 & lt_mask);
                if (((mk0 >> lane) & 1u) && pos < QNS)
                    out[pos] = (float)(j0 + lane);        // exact: < 2^24
                cnt += __popc(mk0);
                if (cnt >= QNS) goto done;
            }
            if (mk1) {   // warp-uniform
                int base = j0 + 32;
                if (cnt == 0) firstj = base + __ffs(mk1) - 1;
                int pos = cnt + __popc(mk1 & lt_mask);
                if (((mk1 >> lane) & 1u) && pos < QNS)
                    out[pos] = (float)(base + lane);
                cnt += __popc(mk1);
                if (cnt >= QNS) goto done;
            }
        }
    }
done:
    if (cnt > QNS) cnt = QNS;
    const float fillv = (cnt > 0) ? (float)firstj : 0.0f;
    for (int s = cnt + lane; s < QNS; s += 32)
        out[s] = fillv;
    if (lane == 0)
        cnt_out[warp_id] = (float)cnt;
}

extern "C" void kernel_launch(void* const* d_in, const int* in_sizes, int n_in,
                              void* d_out, int out_size) {
    const int E1 = QB * 3 * QN;   // 393216 elements (xyz1)
    const int E2 = QB * 3 * QM;   // 49152 elements (xyz2)

    const float* xyz1 = nullptr;
    const float* xyz2 = nullptr;
    for (int i = 0; i < n_in; i++) {
        const int sz = in_sizes[i];
        if ((sz == E1 || sz == E1 * 4) && !xyz1) xyz1 = (const float*)d_in[i];
        else if ((sz == E2 || sz == E2 * 4) && !xyz2) xyz2 = (const float*)d_in[i];
    }
    if ((!xyz1 || !xyz2) && n_in >= 2) {
        if (in_sizes[0] >= in_sizes[1]) {
            if (!xyz1) xyz1 = (const float*)d_in[0];
            if (!xyz2) xyz2 = (const float*)d_in[1];
        } else {
            if (!xyz1) xyz1 = (const float*)d_in[1];
            if (!xyz2) xyz2 = (const float*)d_in[0];
        }
    }
    if (!xyz1 && n_in >= 1) xyz1 = (const float*)d_in[0];
    if (!xyz2) xyz2 = xyz1;

    float* idx_out = (float*)d_out;                  // [0, 1048576)
    float* cnt_out = (float*)d_out + QB * QM * QNS;  // [1048576, 1064960)

    // Kernel 1: per-64-chunk z1 bounds (2048 warps).
    bounds_kernel<<<(QB * NCHUNK * 32 + 255) / 256, 256>>>(xyz1);

    // Kernel 2: query scan, 2-warp blocks for fine-grained tail scheduling.
    const int total_warps = QB * QM;                 // 16384
    const int threads = 64;
    const int blocks = (total_warps * 32 + threads - 1) / threads;   // 8192
    qdp_kernel<<<blocks, threads>>>(xyz1, E1, xyz2, E2, idx_out, cnt_out);
}